// round 7
// baseline (speedup 1.0000x reference)
#include <cuda_runtime.h>

#define U_NODES 60000
#define I_NODES 40000
#define N_NODES 100000   // U + I
#define DIM     128
#define NV      32       // DIM/4 float4 per row
#define NEDGE   2000000

// ---------------- scratch (static device globals; no allocation) -------------
__device__ int   g_cntA[U_NODES];
__device__ int   g_cntB[I_NODES];
__device__ int   g_ptrA[U_NODES + 1];
__device__ int   g_ptrB[I_NODES + 1];
__device__ int   g_curA[U_NODES];
__device__ int   g_curB[I_NODES];
__device__ int   g_colA[NEDGE];
__device__ int   g_colB[NEDGE];
__device__ float g_emb0[N_NODES * DIM];
__device__ float g_emb1[N_NODES * DIM];
__device__ float g_acc [N_NODES * DIM];

// ---------------- kernels ----------------------------------------------------

__global__ void k_zero_counts() {
    int i = blockIdx.x * blockDim.x + threadIdx.x;
    if (i < U_NODES) g_cntA[i] = 0;
    if (i < I_NODES) g_cntB[i] = 0;
}

__global__ void k_count(const int* __restrict__ u, const int* __restrict__ v) {
    int stride = gridDim.x * blockDim.x;
    for (int i = blockIdx.x * blockDim.x + threadIdx.x; i < NEDGE; i += stride) {
        atomicAdd(&g_cntA[u[i]], 1);
        atomicAdd(&g_cntB[v[i]], 1);
    }
}

// single-block exclusive scan (chunked + Hillis-Steele over chunk sums)
__global__ void k_scan(int which) {
    const int* cnt = which ? g_cntB : g_cntA;
    int*       ptr = which ? g_ptrB : g_ptrA;
    int*       cur = which ? g_curB : g_curA;
    const int  n   = which ? I_NODES : U_NODES;

    __shared__ int sh[1024];
    int tid   = threadIdx.x;
    int chunk = (n + 1023) >> 10;
    int s0    = tid * chunk;
    int s1    = s0 + chunk; if (s1 > n) s1 = n;

    int s = 0;
    for (int i = s0; i < s1; i++) s += cnt[i];
    sh[tid] = s;
    __syncthreads();
    for (int d = 1; d < 1024; d <<= 1) {
        int t = (tid >= d) ? sh[tid - d] : 0;
        __syncthreads();
        sh[tid] += t;
        __syncthreads();
    }
    int run = sh[tid] - s;  // exclusive prefix
    for (int i = s0; i < s1; i++) {
        ptr[i] = run;
        cur[i] = run;
        run += cnt[i];
    }
    if (tid == 1023) ptr[n] = sh[1023];
}

__global__ void k_fill(const int* __restrict__ u, const int* __restrict__ v) {
    int stride = gridDim.x * blockDim.x;
    for (int i = blockIdx.x * blockDim.x + threadIdx.x; i < NEDGE; i += stride) {
        int uu = u[i], vv = v[i];
        int pA = atomicAdd(&g_curA[uu], 1);
        g_colA[pA] = vv;
        int pB = atomicAdd(&g_curB[vv], 1);
        g_colB[pB] = uu;
    }
}

__global__ void k_init(const float4* __restrict__ ue, const float4* __restrict__ ie) {
    int i  = blockIdx.x * blockDim.x + threadIdx.x;
    const int nu = U_NODES * NV;
    const int nt = N_NODES * NV;
    if (i >= nt) return;
    float4 e = (i < nu) ? ue[i] : ie[i - nu];
    reinterpret_cast<float4*>(g_emb0)[i] = e;
    reinterpret_cast<float4*>(g_acc)[i]  = e;
}

__device__ __forceinline__ void f4add(float4& a, const float4& b) {
    a.x += b.x; a.y += b.y; a.z += b.z; a.w += b.w;
}

// one warp per row; lane owns one float4 of the 128-wide feature vector
__global__ void __launch_bounds__(256) k_spmm(int parity, int last, float4* __restrict__ out) {
    const float4* s4 = reinterpret_cast<const float4*>(parity ? g_emb1 : g_emb0);
    float4*       d4 = reinterpret_cast<float4*>(parity ? g_emb0 : g_emb1);
    float4*       a4 = reinterpret_cast<float4*>(g_acc);

    int row  = (blockIdx.x * blockDim.x + threadIdx.x) >> 5;
    int lane = threadIdx.x & 31;
    if (row >= N_NODES) return;

    float4 self = s4[row * NV + lane];
    float4 res  = make_float4(0.f, 0.f, 0.f, 0.f);

    if (row < U_NODES) {
        // edge set A: rows = u_id, cols = v_id, scale 1/u_deg[row]
        int beg = g_ptrA[row], end = g_ptrA[row + 1];
        float4 a = make_float4(0.f, 0.f, 0.f, 0.f);
        int j = beg;
        for (; j + 4 <= end; j += 4) {
            int c0 = g_colA[j], c1 = g_colA[j + 1], c2 = g_colA[j + 2], c3 = g_colA[j + 3];
            float4 e0 = s4[c0 * NV + lane];
            float4 e1 = s4[c1 * NV + lane];
            float4 e2 = s4[c2 * NV + lane];
            float4 e3 = s4[c3 * NV + lane];
            f4add(a, e0); f4add(a, e1); f4add(a, e2); f4add(a, e3);
        }
        for (; j < end; j++) {
            float4 e = s4[g_colA[j] * NV + lane];
            f4add(a, e);
        }
        float invA = 1.0f / (float)(end - beg + 1);   // u_deg = cnt + 1
        // self-loop scale for row < U is also 1/u_deg
        res.x = invA * (a.x + self.x);
        res.y = invA * (a.y + self.y);
        res.z = invA * (a.z + self.z);
        res.w = invA * (a.w + self.w);

        if (row < I_NODES) {
            // edge set B: rows = v_id, cols = u_id, scale 1/v_deg[row]
            int bb = g_ptrB[row], be = g_ptrB[row + 1];
            float4 b = make_float4(0.f, 0.f, 0.f, 0.f);
            int k = bb;
            for (; k + 4 <= be; k += 4) {
                int c0 = g_colB[k], c1 = g_colB[k + 1], c2 = g_colB[k + 2], c3 = g_colB[k + 3];
                float4 e0 = s4[c0 * NV + lane];
                float4 e1 = s4[c1 * NV + lane];
                float4 e2 = s4[c2 * NV + lane];
                float4 e3 = s4[c3 * NV + lane];
                f4add(b, e0); f4add(b, e1); f4add(b, e2); f4add(b, e3);
            }
            for (; k < be; k++) {
                float4 e = s4[g_colB[k] * NV + lane];
                f4add(b, e);
            }
            float invB = 1.0f / (float)(be - bb + 1);
            res.x += invB * b.x;
            res.y += invB * b.y;
            res.z += invB * b.z;
            res.w += invB * b.w;
        }
    } else {
        // item nodes >= U get only the self loop (source has no column offset)
        int v = row - U_NODES;
        float invB = 1.0f / (float)(g_ptrB[v + 1] - g_ptrB[v] + 1);
        res.x = invB * self.x;
        res.y = invB * self.y;
        res.z = invB * self.z;
        res.w = invB * self.w;
    }

    int idx = row * NV + lane;
    float4 acc = a4[idx];
    f4add(acc, res);
    if (last) {
        // fused mean over (N_LAYERS + 1) = 4 snapshots
        out[idx] = make_float4(acc.x * 0.25f, acc.y * 0.25f, acc.z * 0.25f, acc.w * 0.25f);
    } else {
        a4[idx] = acc;
        d4[idx] = res;
    }
}

// ---------------- launch ------------------------------------------------------

extern "C" void kernel_launch(void* const* d_in, const int* in_sizes, int n_in,
                              void* d_out, int out_size) {
    const float4* ue = (const float4*)d_in[0];   // user_embedding [U, D] f32
    const float4* ie = (const float4*)d_in[1];   // item_embedding [I, D] f32
    const int*    u  = (const int*)d_in[2];      // u_id [E] i32
    const int*    v  = (const int*)d_in[3];      // v_id [E] i32
    float4*       out = (float4*)d_out;          // [N, D] f32

    // 1) CSR build (reused across all 3 layers)
    k_zero_counts<<<(U_NODES + 255) / 256, 256>>>();
    k_count<<<2048, 256>>>(u, v);
    k_scan<<<1, 1024>>>(0);
    k_scan<<<1, 1024>>>(1);
    k_fill<<<2048, 256>>>(u, v);

    // 2) init embeddings + accumulator
    k_init<<<(N_NODES * NV + 255) / 256, 256>>>(ue, ie);

    // 3) three propagation layers; last one fuses the /4 mean into d_out
    const int spmm_blocks = (N_NODES * 32 + 255) / 256;  // 8 rows per block
    k_spmm<<<spmm_blocks, 256>>>(0, 0, out);
    k_spmm<<<spmm_blocks, 256>>>(1, 0, out);
    k_spmm<<<spmm_blocks, 256>>>(0, 1, out);
}